// round 1
// baseline (speedup 1.0000x reference)
#include <cuda_runtime.h>

// Problem constants
#define BB 4
#define SS 2048
#define DD 1024
#define HH 16
#define HD 64
#define MM (BB*SS)   // 8192

// Scratch (static device allocations are the sanctioned scratch mechanism)
__device__ float g_q[BB*HH*SS*HD];
__device__ float g_k[BB*HH*SS*HD];
__device__ float g_v[BB*HH*SS*HD];
__device__ float g_ctx[BB*SS*DD];

// ---------------------------------------------------------------------------
// GEMM: C = A[M,K] @ W[N,K]^T + bias   (torch Linear)
// BM=BN=128, BK=16, 256 threads, 8x8 micro-tiles.
// QKV=true scatters output into [B,H,S,HD]; else plain [M,N].
// ---------------------------------------------------------------------------
template <bool QKV>
__global__ __launch_bounds__(256)
void gemm_bias_kernel(const float* __restrict__ A,
                      const float* __restrict__ W,
                      const float* __restrict__ bias,
                      float* __restrict__ C)
{
    const int K = DD, N = DD;
    __shared__ float As[16][128];
    __shared__ float Bs[16][128];

    const int tid = threadIdx.x;
    const int tx = tid & 15;        // col group
    const int ty = tid >> 4;        // row group
    const int rowBase = blockIdx.y * 128;
    const int colBase = blockIdx.x * 128;

    const float* Ab = A + (size_t)rowBase * K;
    const float* Wb = W + (size_t)colBase * K;

    // hoist bias for this thread's 8 columns
    float bv[8];
    *(float4*)&bv[0] = *(const float4*)(bias + colBase + tx*8);
    *(float4*)&bv[4] = *(const float4*)(bias + colBase + tx*8 + 4);

    float acc[8][8];
    #pragma unroll
    for (int i = 0; i < 8; i++)
        #pragma unroll
        for (int j = 0; j < 8; j++) acc[i][j] = 0.f;

    for (int kt = 0; kt < K; kt += 16) {
        #pragma unroll
        for (int i = 0; i < 2; i++) {
            int idx = tid + i*256;          // 0..511
            int r   = idx >> 2;             // 0..127
            int kc  = (idx & 3) * 4;        // 0,4,8,12
            float4 av = *(const float4*)(Ab + (size_t)r*K + kt + kc);
            As[kc+0][r] = av.x; As[kc+1][r] = av.y;
            As[kc+2][r] = av.z; As[kc+3][r] = av.w;
            float4 wv = *(const float4*)(Wb + (size_t)r*K + kt + kc);
            Bs[kc+0][r] = wv.x; Bs[kc+1][r] = wv.y;
            Bs[kc+2][r] = wv.z; Bs[kc+3][r] = wv.w;
        }
        __syncthreads();
        #pragma unroll
        for (int k = 0; k < 16; k++) {
            float a[8], b[8];
            *(float4*)&a[0] = *(const float4*)&As[k][ty*8];
            *(float4*)&a[4] = *(const float4*)&As[k][ty*8 + 4];
            *(float4*)&b[0] = *(const float4*)&Bs[k][tx*8];
            *(float4*)&b[4] = *(const float4*)&Bs[k][tx*8 + 4];
            #pragma unroll
            for (int i = 0; i < 8; i++)
                #pragma unroll
                for (int j = 0; j < 8; j++)
                    acc[i][j] += a[i] * b[j];
        }
        __syncthreads();
    }

    // epilogue
    #pragma unroll
    for (int i = 0; i < 8; i++) {
        int m = rowBase + ty*8 + i;
        if (QKV) {
            int b = m >> 11;           // m / S
            int s = m & (SS - 1);
            #pragma unroll
            for (int j = 0; j < 8; j += 4) {
                int n  = colBase + tx*8 + j;
                int h  = n >> 6;
                int hd = n & 63;
                float4 o;
                o.x = acc[i][j+0] + bv[j+0];
                o.y = acc[i][j+1] + bv[j+1];
                o.z = acc[i][j+2] + bv[j+2];
                o.w = acc[i][j+3] + bv[j+3];
                *(float4*)(C + (((size_t)(b*HH + h)*SS + s)*HD + hd)) = o;
            }
        } else {
            #pragma unroll
            for (int j = 0; j < 8; j += 4) {
                int n = colBase + tx*8 + j;
                float4 o;
                o.x = acc[i][j+0] + bv[j+0];
                o.y = acc[i][j+1] + bv[j+1];
                o.z = acc[i][j+2] + bv[j+2];
                o.w = acc[i][j+3] + bv[j+3];
                *(float4*)(C + (size_t)m*N + n) = o;
            }
        }
    }
}

// ---------------------------------------------------------------------------
// Flash-attention (fp32): one CTA per (b*h, q-tile of 64). 256 threads.
// Score phase: 4x4 micro-tiles from transposed Q/K smem.
// Softmax/PV phase: 4 threads per row, 16 output dims per thread.
// Writes ctx directly in [B,S,D] layout.
// ---------------------------------------------------------------------------
__global__ __launch_bounds__(256)
void attn_kernel(const float* __restrict__ Q,
                 const float* __restrict__ Kg,
                 const float* __restrict__ Vg,
                 float* __restrict__ ctx)
{
    extern __shared__ float sm[];
    float* Qst = sm;                 // [64][64]  Qst[d][qrow]
    float* Kst = sm + 64*64;         // [64][64]  Kst[d][key]
    float* Vs  = Kst + 64*64;        // [64][68]  Vs[key][d]
    float* Ss  = Vs  + 64*68;        // [64][68]  scores/probs

    const int tid = threadIdx.x;
    const int bh  = blockIdx.y;
    const int qt  = blockIdx.x;

    const float* Qb = Q  + (size_t)bh * SS * HD + (size_t)qt*64*HD;
    const float* Kb = Kg + (size_t)bh * SS * HD;
    const float* Vb = Vg + (size_t)bh * SS * HD;

    // Load Q tile transposed
    #pragma unroll
    for (int i = 0; i < 4; i++) {
        int idx = tid + i*256;
        int r   = idx >> 4;
        int d0  = (idx & 15) * 4;
        float4 qv = *(const float4*)(Qb + r*HD + d0);
        Qst[(d0+0)*64 + r] = qv.x;
        Qst[(d0+1)*64 + r] = qv.y;
        Qst[(d0+2)*64 + r] = qv.z;
        Qst[(d0+3)*64 + r] = qv.w;
    }

    const int r  = tid >> 2;          // softmax/PV row (0..63)
    const int c  = tid & 3;           // col group (16 dims each)
    const int rr = (tid >> 4) * 4;    // score-phase row base
    const int cc = (tid & 15) * 4;    // score-phase col base

    float mrun = -1e30f, lrun = 0.f;
    float o[16];
    #pragma unroll
    for (int j = 0; j < 16; j++) o[j] = 0.f;

    for (int kt = 0; kt < SS; kt += 64) {
        __syncthreads();   // protect smem reuse from previous iteration + Q load
        // Load K tile transposed, V tile row-major
        #pragma unroll
        for (int i = 0; i < 4; i++) {
            int idx = tid + i*256;
            int row = idx >> 4;
            int d0  = (idx & 15) * 4;
            float4 kv = *(const float4*)(Kb + (size_t)(kt+row)*HD + d0);
            Kst[(d0+0)*64 + row] = kv.x;
            Kst[(d0+1)*64 + row] = kv.y;
            Kst[(d0+2)*64 + row] = kv.z;
            Kst[(d0+3)*64 + row] = kv.w;
            float4 vv = *(const float4*)(Vb + (size_t)(kt+row)*HD + d0);
            *(float4*)(Vs + row*68 + d0) = vv;
        }
        __syncthreads();

        // --- scores: S = Q @ K^T, 4x4 per thread ---
        float sacc[4][4];
        #pragma unroll
        for (int i = 0; i < 4; i++)
            #pragma unroll
            for (int j = 0; j < 4; j++) sacc[i][j] = 0.f;

        #pragma unroll 8
        for (int d = 0; d < 64; d++) {
            float a[4], b[4];
            float4 av = *(const float4*)(Qst + d*64 + rr);
            float4 bv4 = *(const float4*)(Kst + d*64 + cc);
            a[0]=av.x; a[1]=av.y; a[2]=av.z; a[3]=av.w;
            b[0]=bv4.x; b[1]=bv4.y; b[2]=bv4.z; b[3]=bv4.w;
            #pragma unroll
            for (int i = 0; i < 4; i++)
                #pragma unroll
                for (int j = 0; j < 4; j++)
                    sacc[i][j] += a[i] * b[j];
        }
        #pragma unroll
        for (int i = 0; i < 4; i++)
            #pragma unroll
            for (int j = 0; j < 4; j++)
                Ss[(rr+i)*68 + cc + j] = sacc[i][j] * 0.125f;  // 1/sqrt(64)
        __syncthreads();

        // --- online softmax, 4 lanes per row ---
        float tmax = -1e30f;
        #pragma unroll
        for (int j = 0; j < 16; j++)
            tmax = fmaxf(tmax, Ss[r*68 + c*16 + j]);
        tmax = fmaxf(tmax, __shfl_xor_sync(0xffffffffu, tmax, 1));
        tmax = fmaxf(tmax, __shfl_xor_sync(0xffffffffu, tmax, 2));

        float mnew  = fmaxf(mrun, tmax);
        float alpha = __expf(mrun - mnew);
        float lsum = 0.f;
        #pragma unroll
        for (int j = 0; j < 16; j++) {
            float p = __expf(Ss[r*68 + c*16 + j] - mnew);
            Ss[r*68 + c*16 + j] = p;
            lsum += p;
        }
        lsum += __shfl_xor_sync(0xffffffffu, lsum, 1);
        lsum += __shfl_xor_sync(0xffffffffu, lsum, 2);
        lrun = lrun * alpha + lsum;
        mrun = mnew;
        #pragma unroll
        for (int j = 0; j < 16; j++) o[j] *= alpha;
        __syncwarp();   // Ss row writers are the same 4-lane group (same warp)

        // --- PV: o[r][c*16+j] += sum_k P[r][k] * V[k][c*16+j] ---
        #pragma unroll 4
        for (int k0 = 0; k0 < 64; k0 += 4) {
            float4 p4 = *(const float4*)(Ss + r*68 + k0);
            float pk[4] = {p4.x, p4.y, p4.z, p4.w};
            #pragma unroll
            for (int kk = 0; kk < 4; kk++) {
                const float* vrow = Vs + (k0+kk)*68 + c*16;
                float4 v0 = *(const float4*)(vrow);
                float4 v1 = *(const float4*)(vrow + 4);
                float4 v2 = *(const float4*)(vrow + 8);
                float4 v3 = *(const float4*)(vrow + 12);
                o[0]  += pk[kk]*v0.x; o[1]  += pk[kk]*v0.y;
                o[2]  += pk[kk]*v0.z; o[3]  += pk[kk]*v0.w;
                o[4]  += pk[kk]*v1.x; o[5]  += pk[kk]*v1.y;
                o[6]  += pk[kk]*v1.z; o[7]  += pk[kk]*v1.w;
                o[8]  += pk[kk]*v2.x; o[9]  += pk[kk]*v2.y;
                o[10] += pk[kk]*v2.z; o[11] += pk[kk]*v2.w;
                o[12] += pk[kk]*v3.x; o[13] += pk[kk]*v3.y;
                o[14] += pk[kk]*v3.z; o[15] += pk[kk]*v3.w;
            }
        }
    }

    // normalize + write ctx in [B,S,D]
    float inv = 1.f / lrun;
    int qrow = qt*64 + r;
    int b = bh >> 4;    // bh = b*H + h
    int h = bh & 15;
    float* dst = ctx + ((size_t)(b*SS + qrow))*DD + h*64 + c*16;
    #pragma unroll
    for (int j = 0; j < 16; j += 4) {
        float4 w;
        w.x = o[j+0]*inv; w.y = o[j+1]*inv;
        w.z = o[j+2]*inv; w.w = o[j+3]*inv;
        *(float4*)(dst + j) = w;
    }
}

// ---------------------------------------------------------------------------
extern "C" void kernel_launch(void* const* d_in, const int* in_sizes, int n_in,
                              void* d_out, int out_size)
{
    const float* x  = (const float*)d_in[0];
    const float* Wq = (const float*)d_in[1];
    const float* bq = (const float*)d_in[2];
    const float* Wk = (const float*)d_in[3];
    const float* bk = (const float*)d_in[4];
    const float* Wv = (const float*)d_in[5];
    const float* bv = (const float*)d_in[6];
    const float* Wo = (const float*)d_in[7];
    const float* bo = (const float*)d_in[8];

    float *q, *k, *v, *ctx;
    cudaGetSymbolAddress((void**)&q,   g_q);
    cudaGetSymbolAddress((void**)&k,   g_k);
    cudaGetSymbolAddress((void**)&v,   g_v);
    cudaGetSymbolAddress((void**)&ctx, g_ctx);

    const int smem_attn = (64*64*2 + 64*68*2) * sizeof(float);   // 67584
    cudaFuncSetAttribute(attn_kernel,
                         cudaFuncAttributeMaxDynamicSharedMemorySize, smem_attn);

    dim3 ggrid(DD/128, MM/128);   // (8, 64)
    gemm_bias_kernel<true><<<ggrid, 256>>>(x, Wq, bq, q);
    gemm_bias_kernel<true><<<ggrid, 256>>>(x, Wk, bk, k);
    gemm_bias_kernel<true><<<ggrid, 256>>>(x, Wv, bv, v);

    dim3 agrid(SS/64, BB*HH);     // (32, 64)
    attn_kernel<<<agrid, 256, smem_attn>>>(q, k, v, ctx);

    gemm_bias_kernel<false><<<ggrid, 256>>>(ctx, Wo, bo, (float*)d_out);
}

// round 3
// speedup vs baseline: 5.8478x; 5.8478x over previous
#include <cuda_runtime.h>
#include <cstdint>

// Problem constants
#define BB 4
#define SS 2048
#define DD 1024
#define HH 16
#define HD 64
#define MM (BB*SS)   // 8192

// Scratch
__device__ float g_q[BB*HH*SS*HD];
__device__ float g_k[BB*HH*SS*HD];
__device__ float g_v[BB*HH*SS*HD];
__device__ float g_ctx[BB*SS*DD];

// ---------------------------------------------------------------------------
// Helpers (all plain-sm_103-legal PTX: mma.sync tf32 = sm_80+, cp.async = sm_80+)
// ---------------------------------------------------------------------------
__device__ __forceinline__ uint32_t smem_u32(const void* p) {
    uint32_t a;
    asm("{ .reg .u64 t; cvta.to.shared.u64 t, %1; cvt.u32.u64 %0, t; }"
        : "=r"(a) : "l"(p));
    return a;
}

__device__ __forceinline__ uint32_t cvt_tf32(float f) {
    uint32_t o;
    asm("cvt.rn.tf32.f32 %0, %1;" : "=r"(o) : "f"(f));
    return o;
}

// D += A*B, m16n8k8 tf32
__device__ __forceinline__ void mma_tf32(float* d, const uint32_t* a, const uint32_t* b) {
    asm volatile("mma.sync.aligned.m16n8k8.row.col.f32.tf32.tf32.f32 "
        "{%0,%1,%2,%3}, {%4,%5,%6,%7}, {%8,%9}, {%0,%1,%2,%3};"
        : "+f"(d[0]), "+f"(d[1]), "+f"(d[2]), "+f"(d[3])
        : "r"(a[0]), "r"(a[1]), "r"(a[2]), "r"(a[3]), "r"(b[0]), "r"(b[1]));
}

#define CP_ASYNC16(dst, src) \
    asm volatile("cp.async.cg.shared.global [%0], [%1], 16;" :: "r"(dst), "l"(src) : "memory")
#define CP_COMMIT() asm volatile("cp.async.commit_group;" ::: "memory")

// ---------------------------------------------------------------------------
// tf32 warp-MMA GEMM: C = A[M,1024] @ W[1024,1024]^T + bias
// CTA 128x128, 8 warps (64x32 each), BK=32, 3-stage cp.async pipeline.
// smem holds raw fp32; cvt.rn.tf32 at fragment-load time (RN, no trunc bias).
// ---------------------------------------------------------------------------
#define GSTAGE (128*36)   // floats per operand per stage (stride 36 = pad 4)

template <bool QKV>
__global__ __launch_bounds__(256, 2)
void gemm_mma(const float* __restrict__ A, const float* __restrict__ W,
              const float* __restrict__ bias, float* __restrict__ C)
{
    extern __shared__ float smemf[];
    float* As = smemf;                 // 3 stages
    float* Ws = smemf + 3*GSTAGE;
    const uint32_t As_u = smem_u32(As);
    const uint32_t Ws_u = smem_u32(Ws);

    const int tid  = threadIdx.x;
    const int lane = tid & 31, wid = tid >> 5;
    const int q = lane & 3, g = lane >> 2;
    const int mbase = (wid >> 2) * 64;
    const int nbase = (wid & 3) * 32;
    const int rowBase = blockIdx.y * 128;
    const int colBase = blockIdx.x * 128;

    int lr[4], lg[4];
    #pragma unroll
    for (int i = 0; i < 4; i++) { int c = tid + i*256; lr[i] = c >> 3; lg[i] = c & 7; }

    float d[4][4][4];
    #pragma unroll
    for (int mt = 0; mt < 4; mt++)
        #pragma unroll
        for (int nt = 0; nt < 4; nt++)
            #pragma unroll
            for (int e = 0; e < 4; e++) d[mt][nt][e] = 0.f;

    // issue one K-stage of cp.async loads
    auto issue = [&](int kt) {
        const int slot = kt % 3;
        const uint32_t adst = As_u + (uint32_t)(slot * GSTAGE) * 4u;
        const uint32_t wdst = Ws_u + (uint32_t)(slot * GSTAGE) * 4u;
        #pragma unroll
        for (int i = 0; i < 4; i++) {
            const uint32_t off = (uint32_t)(lr[i]*36 + lg[i]*4) * 4u;
            CP_ASYNC16(adst + off, A + (size_t)(rowBase + lr[i])*DD + kt*32 + lg[i]*4);
            CP_ASYNC16(wdst + off, W + (size_t)(colBase + lr[i])*DD + kt*32 + lg[i]*4);
        }
        CP_COMMIT();
    };

    issue(0);
    issue(1);

    for (int kt = 0; kt < 32; kt++) {
        if (kt == 31) asm volatile("cp.async.wait_group 0;" ::: "memory");
        else          asm volatile("cp.async.wait_group 1;" ::: "memory");
        __syncthreads();
        if (kt + 2 < 32) issue(kt + 2);

        const float* A_s = As + (kt % 3) * GSTAGE;
        const float* W_s = Ws + (kt % 3) * GSTAGE;
        #pragma unroll
        for (int ks = 0; ks < 4; ks++) {
            uint32_t af[4][4], bf[4][2];
            #pragma unroll
            for (int mt = 0; mt < 4; mt++) {
                const int r0 = mbase + mt*16 + g;
                af[mt][0] = cvt_tf32(A_s[r0*36      + ks*8 + q]);
                af[mt][1] = cvt_tf32(A_s[(r0+8)*36  + ks*8 + q]);
                af[mt][2] = cvt_tf32(A_s[r0*36      + ks*8 + q + 4]);
                af[mt][3] = cvt_tf32(A_s[(r0+8)*36  + ks*8 + q + 4]);
            }
            #pragma unroll
            for (int nt = 0; nt < 4; nt++) {
                const int n0 = nbase + nt*8 + g;
                bf[nt][0] = cvt_tf32(W_s[n0*36 + ks*8 + q]);
                bf[nt][1] = cvt_tf32(W_s[n0*36 + ks*8 + q + 4]);
            }
            #pragma unroll
            for (int mt = 0; mt < 4; mt++)
                #pragma unroll
                for (int nt = 0; nt < 4; nt++)
                    mma_tf32(d[mt][nt], af[mt], bf[nt]);
        }
    }

    // epilogue: each thread owns (2 rows)x(2 cols) per (mt,nt) tile
    #pragma unroll
    for (int nt = 0; nt < 4; nt++) {
        const int n0 = colBase + nbase + nt*8 + 2*q;
        const float b0 = bias[n0], b1 = bias[n0 + 1];
        #pragma unroll
        for (int mt = 0; mt < 4; mt++) {
            const int m0 = rowBase + mbase + mt*16 + g;
            #pragma unroll
            for (int half = 0; half < 2; half++) {
                const int m = m0 + half*8;
                float2 o;
                o.x = d[mt][nt][half*2 + 0] + b0;
                o.y = d[mt][nt][half*2 + 1] + b1;
                if (QKV) {
                    const int b  = m >> 11;
                    const int s  = m & (SS - 1);
                    const int h  = n0 >> 6;
                    const int hd = n0 & 63;
                    *(float2*)(C + (((size_t)(b*HH + h)*SS + s)*HD + hd)) = o;
                } else {
                    *(float2*)(C + (size_t)m*DD + n0) = o;
                }
            }
        }
    }
}

// ---------------------------------------------------------------------------
// tf32 warp-MMA flash-attention.
// CTA = 128 q-rows x one (b,h); 8 warps, each owns an m16 stripe (softmax
// stays warp-local). KV tiles of 64. QK^T and PV via m16n8k8; P via smem.
// ---------------------------------------------------------------------------
__global__ __launch_bounds__(256, 2)
void attn_mma(const float* __restrict__ Q, const float* __restrict__ K,
              const float* __restrict__ V, float* __restrict__ ctx)
{
    extern __shared__ float sf[];
    float* Qs = sf;                    // [128][68], pre-scaled, tf32 bits
    float* Ks = sf + 128*68;           // [64][68]
    float* Vs = Ks + 64*68;            // [64][68]
    float* Ps = Vs + 64*68;            // [128][68]

    const int tid  = threadIdx.x;
    const int lane = tid & 31, wid = tid >> 5;
    const int q = lane & 3, g = lane >> 2;
    const int bh = blockIdx.y, qt = blockIdx.x;

    const float* Qb = Q + (size_t)bh*SS*HD + (size_t)qt*128*HD;
    const float* Kb = K + (size_t)bh*SS*HD;
    const float* Vb = V + (size_t)bh*SS*HD;

    // load + scale + tf32-round Q (once)
    #pragma unroll
    for (int i = 0; i < 8; i++) {
        const int c = tid + i*256;
        const int r = c >> 4, d0 = (c & 15) * 4;
        float4 v = *(const float4*)(Qb + r*HD + d0);
        Qs[r*68 + d0 + 0] = __uint_as_float(cvt_tf32(v.x * 0.125f));
        Qs[r*68 + d0 + 1] = __uint_as_float(cvt_tf32(v.y * 0.125f));
        Qs[r*68 + d0 + 2] = __uint_as_float(cvt_tf32(v.z * 0.125f));
        Qs[r*68 + d0 + 3] = __uint_as_float(cvt_tf32(v.w * 0.125f));
    }

    const int r0 = wid*16 + g;        // this thread's first row (second = r0+8)

    float m0 = -1e30f, m1 = -1e30f, l0 = 0.f, l1 = 0.f;
    float o[8][4];
    #pragma unroll
    for (int nt = 0; nt < 8; nt++)
        #pragma unroll
        for (int e = 0; e < 4; e++) o[nt][e] = 0.f;

    for (int kt = 0; kt < SS/64; kt++) {
        __syncthreads();
        // load K, V tiles (cvt at store; each element converted once)
        #pragma unroll
        for (int i = 0; i < 4; i++) {
            const int c = tid + i*256;
            const int r = c >> 4, d0 = (c & 15) * 4;
            float4 kv = *(const float4*)(Kb + (size_t)(kt*64 + r)*HD + d0);
            Ks[r*68 + d0 + 0] = __uint_as_float(cvt_tf32(kv.x));
            Ks[r*68 + d0 + 1] = __uint_as_float(cvt_tf32(kv.y));
            Ks[r*68 + d0 + 2] = __uint_as_float(cvt_tf32(kv.z));
            Ks[r*68 + d0 + 3] = __uint_as_float(cvt_tf32(kv.w));
            float4 vv = *(const float4*)(Vb + (size_t)(kt*64 + r)*HD + d0);
            Vs[r*68 + d0 + 0] = __uint_as_float(cvt_tf32(vv.x));
            Vs[r*68 + d0 + 1] = __uint_as_float(cvt_tf32(vv.y));
            Vs[r*68 + d0 + 2] = __uint_as_float(cvt_tf32(vv.z));
            Vs[r*68 + d0 + 3] = __uint_as_float(cvt_tf32(vv.w));
        }
        __syncthreads();

        // --- QK^T: S stripe [16][64] per warp ---
        float s[8][4];
        #pragma unroll
        for (int nt = 0; nt < 8; nt++)
            #pragma unroll
            for (int e = 0; e < 4; e++) s[nt][e] = 0.f;

        #pragma unroll
        for (int ks = 0; ks < 8; ks++) {
            uint32_t a[4];
            a[0] = __float_as_uint(Qs[r0*68     + ks*8 + q]);
            a[1] = __float_as_uint(Qs[(r0+8)*68 + ks*8 + q]);
            a[2] = __float_as_uint(Qs[r0*68     + ks*8 + q + 4]);
            a[3] = __float_as_uint(Qs[(r0+8)*68 + ks*8 + q + 4]);
            #pragma unroll
            for (int nt = 0; nt < 8; nt++) {
                uint32_t b[2];
                b[0] = __float_as_uint(Ks[(nt*8 + g)*68 + ks*8 + q]);
                b[1] = __float_as_uint(Ks[(nt*8 + g)*68 + ks*8 + q + 4]);
                mma_tf32(s[nt], a, b);
            }
        }

        // --- online softmax (rows r0 and r0+8; 4 lanes per row) ---
        float mx0 = -1e30f, mx1 = -1e30f;
        #pragma unroll
        for (int nt = 0; nt < 8; nt++) {
            mx0 = fmaxf(mx0, fmaxf(s[nt][0], s[nt][1]));
            mx1 = fmaxf(mx1, fmaxf(s[nt][2], s[nt][3]));
        }
        mx0 = fmaxf(mx0, __shfl_xor_sync(0xffffffffu, mx0, 1));
        mx0 = fmaxf(mx0, __shfl_xor_sync(0xffffffffu, mx0, 2));
        mx1 = fmaxf(mx1, __shfl_xor_sync(0xffffffffu, mx1, 1));
        mx1 = fmaxf(mx1, __shfl_xor_sync(0xffffffffu, mx1, 2));

        const float mn0 = fmaxf(m0, mx0), mn1 = fmaxf(m1, mx1);
        const float al0 = __expf(m0 - mn0), al1 = __expf(m1 - mn1);

        float sum0 = 0.f, sum1 = 0.f;
        #pragma unroll
        for (int nt = 0; nt < 8; nt++) {
            s[nt][0] = __expf(s[nt][0] - mn0);
            s[nt][1] = __expf(s[nt][1] - mn0);
            s[nt][2] = __expf(s[nt][2] - mn1);
            s[nt][3] = __expf(s[nt][3] - mn1);
            sum0 += s[nt][0] + s[nt][1];
            sum1 += s[nt][2] + s[nt][3];
        }
        sum0 += __shfl_xor_sync(0xffffffffu, sum0, 1);
        sum0 += __shfl_xor_sync(0xffffffffu, sum0, 2);
        sum1 += __shfl_xor_sync(0xffffffffu, sum1, 1);
        sum1 += __shfl_xor_sync(0xffffffffu, sum1, 2);

        l0 = l0 * al0 + sum0;  m0 = mn0;
        l1 = l1 * al1 + sum1;  m1 = mn1;

        #pragma unroll
        for (int nt = 0; nt < 8; nt++) {
            o[nt][0] *= al0; o[nt][1] *= al0;
            o[nt][2] *= al1; o[nt][3] *= al1;
        }

        // store P (tf32 bits) to own stripe — warp-local
        #pragma unroll
        for (int nt = 0; nt < 8; nt++) {
            float2 p0, p1;
            p0.x = __uint_as_float(cvt_tf32(s[nt][0]));
            p0.y = __uint_as_float(cvt_tf32(s[nt][1]));
            p1.x = __uint_as_float(cvt_tf32(s[nt][2]));
            p1.y = __uint_as_float(cvt_tf32(s[nt][3]));
            *(float2*)(Ps + r0*68     + nt*8 + 2*q) = p0;
            *(float2*)(Ps + (r0+8)*68 + nt*8 + 2*q) = p1;
        }
        __syncwarp();

        // --- PV: o += P[16x64] @ V[64x64] ---
        #pragma unroll
        for (int ks = 0; ks < 8; ks++) {
            uint32_t a[4];
            a[0] = __float_as_uint(Ps[r0*68     + ks*8 + q]);
            a[1] = __float_as_uint(Ps[(r0+8)*68 + ks*8 + q]);
            a[2] = __float_as_uint(Ps[r0*68     + ks*8 + q + 4]);
            a[3] = __float_as_uint(Ps[(r0+8)*68 + ks*8 + q + 4]);
            #pragma unroll
            for (int nt = 0; nt < 8; nt++) {
                uint32_t b[2];
                b[0] = __float_as_uint(Vs[(ks*8 + q)*68     + nt*8 + g]);
                b[1] = __float_as_uint(Vs[(ks*8 + q + 4)*68 + nt*8 + g]);
                mma_tf32(o[nt], a, b);
            }
        }
    }

    // normalize + write ctx in [B,S,D]
    const float inv0 = 1.f / l0, inv1 = 1.f / l1;
    const int b = bh >> 4, h = bh & 15;
    const int row0 = qt*128 + r0;
    float* dst0 = ctx + ((size_t)(b*SS + row0))*DD + h*64;
    float* dst1 = ctx + ((size_t)(b*SS + row0 + 8))*DD + h*64;
    #pragma unroll
    for (int nt = 0; nt < 8; nt++) {
        float2 w0, w1;
        w0.x = o[nt][0]*inv0; w0.y = o[nt][1]*inv0;
        w1.x = o[nt][2]*inv1; w1.y = o[nt][3]*inv1;
        *(float2*)(dst0 + nt*8 + 2*q) = w0;
        *(float2*)(dst1 + nt*8 + 2*q) = w1;
    }
}

// ---------------------------------------------------------------------------
extern "C" void kernel_launch(void* const* d_in, const int* in_sizes, int n_in,
                              void* d_out, int out_size)
{
    const float* x  = (const float*)d_in[0];
    const float* Wq = (const float*)d_in[1];
    const float* bq = (const float*)d_in[2];
    const float* Wk = (const float*)d_in[3];
    const float* bk = (const float*)d_in[4];
    const float* Wv = (const float*)d_in[5];
    const float* bv = (const float*)d_in[6];
    const float* Wo = (const float*)d_in[7];
    const float* bo = (const float*)d_in[8];

    float *q, *k, *v, *ctx;
    cudaGetSymbolAddress((void**)&q,   g_q);
    cudaGetSymbolAddress((void**)&k,   g_k);
    cudaGetSymbolAddress((void**)&v,   g_v);
    cudaGetSymbolAddress((void**)&ctx, g_ctx);

    const int smem_gemm = 3 * GSTAGE * 2 * sizeof(float);          // 110592
    const int smem_attn = (128*68*2 + 64*68*2) * sizeof(float);    // 104448
    cudaFuncSetAttribute(gemm_mma<true>,
                         cudaFuncAttributeMaxDynamicSharedMemorySize, smem_gemm);
    cudaFuncSetAttribute(gemm_mma<false>,
                         cudaFuncAttributeMaxDynamicSharedMemorySize, smem_gemm);
    cudaFuncSetAttribute(attn_mma,
                         cudaFuncAttributeMaxDynamicSharedMemorySize, smem_attn);

    dim3 ggrid(DD/128, MM/128);   // (8, 64)
    gemm_mma<true><<<ggrid, 256, smem_gemm>>>(x, Wq, bq, q);
    gemm_mma<true><<<ggrid, 256, smem_gemm>>>(x, Wk, bk, k);
    gemm_mma<true><<<ggrid, 256, smem_gemm>>>(x, Wv, bv, v);

    dim3 agrid(SS/128, BB*HH);    // (16, 64)
    attn_mma<<<agrid, 256, smem_attn>>>(q, k, v, ctx);

    gemm_mma<false><<<ggrid, 256, smem_gemm>>>(ctx, Wo, bo, (float*)d_out);
}

// round 4
// speedup vs baseline: 7.0001x; 1.1970x over previous
#include <cuda_runtime.h>
#include <cstdint>

// Problem constants
#define BB 4
#define SS 2048
#define DD 1024
#define HH 16
#define HD 64
#define MM (BB*SS)   // 8192

// Scratch
__device__ float g_q[BB*HH*SS*HD];
__device__ float g_k[BB*HH*SS*HD];
__device__ float g_v[BB*HH*SS*HD];
__device__ float g_ctx[BB*SS*DD];

// ---------------------------------------------------------------------------
// Helpers (plain-sm_103-legal PTX only)
// ---------------------------------------------------------------------------
__device__ __forceinline__ uint32_t smem_u32(const void* p) {
    uint32_t a;
    asm("{ .reg .u64 t; cvta.to.shared.u64 t, %1; cvt.u32.u64 %0, t; }"
        : "=r"(a) : "l"(p));
    return a;
}

__device__ __forceinline__ uint32_t cvt_tf32(float f) {
    uint32_t o;
    asm("cvt.rn.tf32.f32 %0, %1;" : "=r"(o) : "f"(f));
    return o;
}

__device__ __forceinline__ void mma_tf32(float* d, const uint32_t* a, const uint32_t* b) {
    asm volatile("mma.sync.aligned.m16n8k8.row.col.f32.tf32.tf32.f32 "
        "{%0,%1,%2,%3}, {%4,%5,%6,%7}, {%8,%9}, {%0,%1,%2,%3};"
        : "+f"(d[0]), "+f"(d[1]), "+f"(d[2]), "+f"(d[3])
        : "r"(a[0]), "r"(a[1]), "r"(a[2]), "r"(a[3]), "r"(b[0]), "r"(b[1]));
}

#define CP_ASYNC16(dst, src) \
    asm volatile("cp.async.cg.shared.global [%0], [%1], 16;" :: "r"(dst), "l"(src) : "memory")
#define CP_COMMIT() asm volatile("cp.async.commit_group;" ::: "memory")
#define CP_WAIT0()  asm volatile("cp.async.wait_group 0;" ::: "memory")
#define CP_WAIT1()  asm volatile("cp.async.wait_group 1;" ::: "memory")

// ---------------------------------------------------------------------------
// tf32 warp-MMA GEMM body: C = A[M,1024] @ W[1024,1024]^T + bias
// CTA 128x128, 8 warps (64x32 each), BK=32, 3-stage cp.async pipeline.
// ---------------------------------------------------------------------------
#define GSTAGE (128*36)

template <bool QKV>
__device__ __forceinline__
void gemm_body(float* smemf,
               const float* __restrict__ A, const float* __restrict__ W,
               const float* __restrict__ bias, float* __restrict__ C)
{
    float* As = smemf;
    float* Ws = smemf + 3*GSTAGE;
    const uint32_t As_u = smem_u32(As);
    const uint32_t Ws_u = smem_u32(Ws);

    const int tid  = threadIdx.x;
    const int lane = tid & 31, wid = tid >> 5;
    const int q = lane & 3, g = lane >> 2;
    const int mbase = (wid >> 2) * 64;
    const int nbase = (wid & 3) * 32;
    const int rowBase = blockIdx.y * 128;
    const int colBase = blockIdx.x * 128;

    int lr[4], lg[4];
    #pragma unroll
    for (int i = 0; i < 4; i++) { int c = tid + i*256; lr[i] = c >> 3; lg[i] = c & 7; }

    float d[4][4][4];
    #pragma unroll
    for (int mt = 0; mt < 4; mt++)
        #pragma unroll
        for (int nt = 0; nt < 4; nt++)
            #pragma unroll
            for (int e = 0; e < 4; e++) d[mt][nt][e] = 0.f;

    auto issue = [&](int kt) {
        const int slot = kt % 3;
        const uint32_t adst = As_u + (uint32_t)(slot * GSTAGE) * 4u;
        const uint32_t wdst = Ws_u + (uint32_t)(slot * GSTAGE) * 4u;
        #pragma unroll
        for (int i = 0; i < 4; i++) {
            const uint32_t off = (uint32_t)(lr[i]*36 + lg[i]*4) * 4u;
            CP_ASYNC16(adst + off, A + (size_t)(rowBase + lr[i])*DD + kt*32 + lg[i]*4);
            CP_ASYNC16(wdst + off, W + (size_t)(colBase + lr[i])*DD + kt*32 + lg[i]*4);
        }
        CP_COMMIT();
    };

    issue(0);
    issue(1);

    for (int kt = 0; kt < 32; kt++) {
        if (kt == 31) CP_WAIT0(); else CP_WAIT1();
        __syncthreads();
        if (kt + 2 < 32) issue(kt + 2);

        const float* A_s = As + (kt % 3) * GSTAGE;
        const float* W_s = Ws + (kt % 3) * GSTAGE;
        #pragma unroll
        for (int ks = 0; ks < 4; ks++) {
            uint32_t af[4][4], bf[4][2];
            #pragma unroll
            for (int mt = 0; mt < 4; mt++) {
                const int r0 = mbase + mt*16 + g;
                af[mt][0] = cvt_tf32(A_s[r0*36      + ks*8 + q]);
                af[mt][1] = cvt_tf32(A_s[(r0+8)*36  + ks*8 + q]);
                af[mt][2] = cvt_tf32(A_s[r0*36      + ks*8 + q + 4]);
                af[mt][3] = cvt_tf32(A_s[(r0+8)*36  + ks*8 + q + 4]);
            }
            #pragma unroll
            for (int nt = 0; nt < 4; nt++) {
                const int n0 = nbase + nt*8 + g;
                bf[nt][0] = cvt_tf32(W_s[n0*36 + ks*8 + q]);
                bf[nt][1] = cvt_tf32(W_s[n0*36 + ks*8 + q + 4]);
            }
            #pragma unroll
            for (int mt = 0; mt < 4; mt++)
                #pragma unroll
                for (int nt = 0; nt < 4; nt++)
                    mma_tf32(d[mt][nt], af[mt], bf[nt]);
        }
    }

    #pragma unroll
    for (int nt = 0; nt < 4; nt++) {
        const int n0 = colBase + nbase + nt*8 + 2*q;
        const float b0 = bias[n0], b1 = bias[n0 + 1];
        #pragma unroll
        for (int mt = 0; mt < 4; mt++) {
            const int m0 = rowBase + mbase + mt*16 + g;
            #pragma unroll
            for (int half = 0; half < 2; half++) {
                const int m = m0 + half*8;
                float2 o;
                o.x = d[mt][nt][half*2 + 0] + b0;
                o.y = d[mt][nt][half*2 + 1] + b1;
                if (QKV) {
                    const int b  = m >> 11;
                    const int s  = m & (SS - 1);
                    const int h  = n0 >> 6;
                    const int hd = n0 & 63;
                    *(float2*)(C + (((size_t)(b*HH + h)*SS + s)*HD + hd)) = o;
                } else {
                    *(float2*)(C + (size_t)m*DD + n0) = o;
                }
            }
        }
    }
}

// Fused Q/K/V projection: blockIdx.z selects the weight/bias/dst triple.
__global__ __launch_bounds__(256, 2)
void gemm_qkv(const float* __restrict__ A,
              const float* __restrict__ W0, const float* __restrict__ W1,
              const float* __restrict__ W2,
              const float* __restrict__ b0, const float* __restrict__ b1,
              const float* __restrict__ b2,
              float* __restrict__ C0, float* __restrict__ C1, float* __restrict__ C2)
{
    extern __shared__ float smemf[];
    const int z = blockIdx.z;
    const float* W = (z == 0) ? W0 : (z == 1) ? W1 : W2;
    const float* b = (z == 0) ? b0 : (z == 1) ? b1 : b2;
    float*       C = (z == 0) ? C0 : (z == 1) ? C1 : C2;
    gemm_body<true>(smemf, A, W, b, C);
}

__global__ __launch_bounds__(256, 2)
void gemm_out(const float* __restrict__ A, const float* __restrict__ W,
              const float* __restrict__ bias, float* __restrict__ C)
{
    extern __shared__ float smemf[];
    gemm_body<false>(smemf, A, W, bias, C);
}

// ---------------------------------------------------------------------------
// tf32 warp-MMA flash-attention, v2.
//  - Q resident in smem, pair-permuted stride-72 layout -> conflict-free v2
//    a-fragment loads.
//  - K/V double-buffered via cp.async (raw fp32; cvt.rn at fragment load).
//    K row stride 68, V row stride 72: conflict-free b-fragment loads.
//  - P never touches smem: S c-frag -> PV a-frag via warp shuffles.
// ---------------------------------------------------------------------------
#define KSTR 68
#define VSTR 72
#define QSTR 72
#define KBUF (64*KSTR)   // 4352 floats
#define VBUF (64*VSTR)   // 4608 floats

__global__ __launch_bounds__(256, 2)
void attn_mma(const float* __restrict__ Q, const float* __restrict__ K,
              const float* __restrict__ V, float* __restrict__ ctx)
{
    extern __shared__ float sf[];
    float* Qs = sf;                    // [128][72] permuted-pair layout
    float* Ks = sf + 128*QSTR;         // [2][64][68] raw fp32
    float* Vs = Ks + 2*KBUF;           // [2][64][72] raw fp32
    const uint32_t Ks_u = smem_u32(Ks);
    const uint32_t Vs_u = smem_u32(Vs);

    const int tid  = threadIdx.x;
    const int lane = tid & 31, wid = tid >> 5;
    const int q = lane & 3, g = lane >> 2;
    const int bh = blockIdx.y, qt = blockIdx.x;

    const float* Qb = Q + (size_t)bh*SS*HD + (size_t)qt*128*HD;
    const float* Kb = K + (size_t)bh*SS*HD;
    const float* Vb = V + (size_t)bh*SS*HD;

    // Q: load once, scale by 1/8, tf32-RN round, store pair-permuted.
    // col c -> pos (c & ~7) + ((c&4)?1:0) + 2*(c&3)
    #pragma unroll
    for (int i = 0; i < 8; i++) {
        const int c = tid + i*256;
        const int r = c >> 4, d0 = (c & 15) * 4;
        float4 v = *(const float4*)(Qb + r*HD + d0);
        const int base = (d0 & ~7) + ((d0 & 4) ? 1 : 0);
        Qs[r*QSTR + base + 0] = __uint_as_float(cvt_tf32(v.x * 0.125f));
        Qs[r*QSTR + base + 2] = __uint_as_float(cvt_tf32(v.y * 0.125f));
        Qs[r*QSTR + base + 4] = __uint_as_float(cvt_tf32(v.z * 0.125f));
        Qs[r*QSTR + base + 6] = __uint_as_float(cvt_tf32(v.w * 0.125f));
    }

    auto issue_kv = [&](int kt) {
        const int buf = kt & 1;
        #pragma unroll
        for (int i = 0; i < 4; i++) {
            const int c = tid + i*256;
            const int r = c >> 4, d0 = (c & 15) * 4;
            CP_ASYNC16(Ks_u + (uint32_t)(buf*KBUF + r*KSTR + d0)*4u,
                       Kb + (size_t)(kt*64 + r)*HD + d0);
            CP_ASYNC16(Vs_u + (uint32_t)(buf*VBUF + r*VSTR + d0)*4u,
                       Vb + (size_t)(kt*64 + r)*HD + d0);
        }
        CP_COMMIT();
    };

    const int r0 = wid*16 + g;

    float m0 = -1e30f, m1 = -1e30f, l0 = 0.f, l1 = 0.f;
    float o[8][4];
    #pragma unroll
    for (int nt = 0; nt < 8; nt++)
        #pragma unroll
        for (int e = 0; e < 4; e++) o[nt][e] = 0.f;

    issue_kv(0);

    const int srcA = (lane & ~3) | (q >> 1);
    const int srcB = srcA + 2;
    const bool hi  = (q & 1) != 0;

    for (int kt = 0; kt < SS/64; kt++) {
        CP_WAIT0();
        __syncthreads();     // kt data visible; buffer (kt+1)&1 free (prev compute done)
        if (kt + 1 < SS/64) issue_kv(kt + 1);

        const float* Kc = Ks + (kt & 1) * KBUF;
        const float* Vc = Vs + (kt & 1) * VBUF;

        // --- QK^T: S stripe [16][64] per warp ---
        float s[8][4];
        #pragma unroll
        for (int nt = 0; nt < 8; nt++)
            #pragma unroll
            for (int e = 0; e < 4; e++) s[nt][e] = 0.f;

        #pragma unroll
        for (int ks = 0; ks < 8; ks++) {
            uint32_t a[4];
            float2 qa = *(const float2*)(Qs + r0*QSTR     + ks*8 + 2*q);
            float2 qb = *(const float2*)(Qs + (r0+8)*QSTR + ks*8 + 2*q);
            a[0] = __float_as_uint(qa.x);
            a[1] = __float_as_uint(qb.x);
            a[2] = __float_as_uint(qa.y);
            a[3] = __float_as_uint(qb.y);
            #pragma unroll
            for (int nt = 0; nt < 8; nt++) {
                uint32_t b[2];
                b[0] = cvt_tf32(Kc[(nt*8 + g)*KSTR + ks*8 + q]);
                b[1] = cvt_tf32(Kc[(nt*8 + g)*KSTR + ks*8 + q + 4]);
                mma_tf32(s[nt], a, b);
            }
        }

        // --- online softmax (rows r0, r0+8; 4 lanes per row) ---
        float mx0 = -1e30f, mx1 = -1e30f;
        #pragma unroll
        for (int nt = 0; nt < 8; nt++) {
            mx0 = fmaxf(mx0, fmaxf(s[nt][0], s[nt][1]));
            mx1 = fmaxf(mx1, fmaxf(s[nt][2], s[nt][3]));
        }
        mx0 = fmaxf(mx0, __shfl_xor_sync(0xffffffffu, mx0, 1));
        mx0 = fmaxf(mx0, __shfl_xor_sync(0xffffffffu, mx0, 2));
        mx1 = fmaxf(mx1, __shfl_xor_sync(0xffffffffu, mx1, 1));
        mx1 = fmaxf(mx1, __shfl_xor_sync(0xffffffffu, mx1, 2));

        const float mn0 = fmaxf(m0, mx0), mn1 = fmaxf(m1, mx1);
        const float al0 = __expf(m0 - mn0), al1 = __expf(m1 - mn1);

        float sum0 = 0.f, sum1 = 0.f;
        #pragma unroll
        for (int nt = 0; nt < 8; nt++) {
            s[nt][0] = __expf(s[nt][0] - mn0);
            s[nt][1] = __expf(s[nt][1] - mn0);
            s[nt][2] = __expf(s[nt][2] - mn1);
            s[nt][3] = __expf(s[nt][3] - mn1);
            sum0 += s[nt][0] + s[nt][1];
            sum1 += s[nt][2] + s[nt][3];
        }
        sum0 += __shfl_xor_sync(0xffffffffu, sum0, 1);
        sum0 += __shfl_xor_sync(0xffffffffu, sum0, 2);
        sum1 += __shfl_xor_sync(0xffffffffu, sum1, 1);
        sum1 += __shfl_xor_sync(0xffffffffu, sum1, 2);

        l0 = l0 * al0 + sum0;  m0 = mn0;
        l1 = l1 * al1 + sum1;  m1 = mn1;

        #pragma unroll
        for (int nt = 0; nt < 8; nt++) {
            o[nt][0] *= al0; o[nt][1] *= al0;
            o[nt][2] *= al1; o[nt][3] *= al1;
        }

        // --- PV: o += P[16x64] @ V[64x64]; a-frag via shuffles from s ---
        #pragma unroll
        for (int ks = 0; ks < 8; ks++) {
            const float e0 = s[ks][0], e1 = s[ks][1], e2 = s[ks][2], e3 = s[ks][3];
            const float v0a = __shfl_sync(0xffffffffu, e0, srcA);
            const float v1a = __shfl_sync(0xffffffffu, e1, srcA);
            const float v0b = __shfl_sync(0xffffffffu, e0, srcB);
            const float v1b = __shfl_sync(0xffffffffu, e1, srcB);
            const float v2a = __shfl_sync(0xffffffffu, e2, srcA);
            const float v3a = __shfl_sync(0xffffffffu, e3, srcA);
            const float v2b = __shfl_sync(0xffffffffu, e2, srcB);
            const float v3b = __shfl_sync(0xffffffffu, e3, srcB);
            uint32_t a[4];
            a[0] = cvt_tf32(hi ? v1a : v0a);
            a[1] = cvt_tf32(hi ? v3a : v2a);
            a[2] = cvt_tf32(hi ? v1b : v0b);
            a[3] = cvt_tf32(hi ? v3b : v2b);
            #pragma unroll
            for (int nt = 0; nt < 8; nt++) {
                uint32_t b[2];
                b[0] = cvt_tf32(Vc[(ks*8 + q)*VSTR     + nt*8 + g]);
                b[1] = cvt_tf32(Vc[(ks*8 + q + 4)*VSTR + nt*8 + g]);
                mma_tf32(o[nt], a, b);
            }
        }
    }

    // normalize + write ctx in [B,S,D]
    const float inv0 = 1.f / l0, inv1 = 1.f / l1;
    const int b = bh >> 4, h = bh & 15;
    const int row0 = qt*128 + r0;
    float* dst0 = ctx + ((size_t)(b*SS + row0))*DD + h*64;
    float* dst1 = ctx + ((size_t)(b*SS + row0 + 8))*DD + h*64;
    #pragma unroll
    for (int nt = 0; nt < 8; nt++) {
        float2 w0, w1;
        w0.x = o[nt][0]*inv0; w0.y = o[nt][1]*inv0;
        w1.x = o[nt][2]*inv1; w1.y = o[nt][3]*inv1;
        *(float2*)(dst0 + nt*8 + 2*q) = w0;
        *(float2*)(dst1 + nt*8 + 2*q) = w1;
    }
}

// ---------------------------------------------------------------------------
extern "C" void kernel_launch(void* const* d_in, const int* in_sizes, int n_in,
                              void* d_out, int out_size)
{
    const float* x  = (const float*)d_in[0];
    const float* Wq = (const float*)d_in[1];
    const float* bq = (const float*)d_in[2];
    const float* Wk = (const float*)d_in[3];
    const float* bk = (const float*)d_in[4];
    const float* Wv = (const float*)d_in[5];
    const float* bv = (const float*)d_in[6];
    const float* Wo = (const float*)d_in[7];
    const float* bo = (const float*)d_in[8];

    float *q, *k, *v, *ctx;
    cudaGetSymbolAddress((void**)&q,   g_q);
    cudaGetSymbolAddress((void**)&k,   g_k);
    cudaGetSymbolAddress((void**)&v,   g_v);
    cudaGetSymbolAddress((void**)&ctx, g_ctx);

    const int smem_gemm = 3 * GSTAGE * 2 * sizeof(float);               // 110592
    const int smem_attn = (128*QSTR + 2*KBUF + 2*VBUF) * sizeof(float); // 108544
    cudaFuncSetAttribute(gemm_qkv,
                         cudaFuncAttributeMaxDynamicSharedMemorySize, smem_gemm);
    cudaFuncSetAttribute(gemm_out,
                         cudaFuncAttributeMaxDynamicSharedMemorySize, smem_gemm);
    cudaFuncSetAttribute(attn_mma,
                         cudaFuncAttributeMaxDynamicSharedMemorySize, smem_attn);

    dim3 qkvgrid(DD/128, MM/128, 3);   // (8, 64, 3)
    gemm_qkv<<<qkvgrid, 256, smem_gemm>>>(x, Wq, Wk, Wv, bq, bk, bv, q, k, v);

    dim3 agrid(SS/128, BB*HH);         // (16, 64)
    attn_mma<<<agrid, 256, smem_attn>>>(q, k, v, ctx);

    dim3 ogrid(DD/128, MM/128);        // (8, 64)
    gemm_out<<<ogrid, 256, smem_gemm>>>(ctx, Wo, bo, (float*)d_out);
}

// round 5
// speedup vs baseline: 7.3902x; 1.0557x over previous
#include <cuda_runtime.h>
#include <cstdint>

// Problem constants
#define BB 4
#define SS 2048
#define DD 1024
#define HH 16
#define HD 64
#define MM (BB*SS)   // 8192

// Scratch
__device__ float g_q[BB*HH*SS*HD];
__device__ float g_k[BB*HH*SS*HD];
__device__ float g_v[BB*HH*SS*HD];
__device__ float g_ctx[BB*SS*DD];
__device__ float g_xr[MM*DD];        // tf32-rounded x
__device__ float g_wr[4*DD*DD];      // tf32-rounded Wq|Wk|Wv|Wo

// ---------------------------------------------------------------------------
// Helpers (plain-sm_103-legal PTX only)
// ---------------------------------------------------------------------------
__device__ __forceinline__ uint32_t smem_u32(const void* p) {
    uint32_t a;
    asm("{ .reg .u64 t; cvta.to.shared.u64 t, %1; cvt.u32.u64 %0, t; }"
        : "=r"(a) : "l"(p));
    return a;
}

__device__ __forceinline__ uint32_t cvt_tf32(float f) {
    uint32_t o;
    asm("cvt.rn.tf32.f32 %0, %1;" : "=r"(o) : "f"(f));
    return o;
}

__device__ __forceinline__ void mma_tf32(float* d, const uint32_t* a, const uint32_t* b) {
    asm volatile("mma.sync.aligned.m16n8k8.row.col.f32.tf32.tf32.f32 "
        "{%0,%1,%2,%3}, {%4,%5,%6,%7}, {%8,%9}, {%0,%1,%2,%3};"
        : "+f"(d[0]), "+f"(d[1]), "+f"(d[2]), "+f"(d[3])
        : "r"(a[0]), "r"(a[1]), "r"(a[2]), "r"(a[3]), "r"(b[0]), "r"(b[1]));
}

#define CP_ASYNC16(dst, src) \
    asm volatile("cp.async.cg.shared.global [%0], [%1], 16;" :: "r"(dst), "l"(src) : "memory")
#define CP_COMMIT() asm volatile("cp.async.commit_group;" ::: "memory")
#define CP_WAIT0()  asm volatile("cp.async.wait_group 0;" ::: "memory")
#define CP_WAIT1()  asm volatile("cp.async.wait_group 1;" ::: "memory")

// ---------------------------------------------------------------------------
// Prep: RN-round x and the 4 weight matrices to tf32 (one pass, once).
// ---------------------------------------------------------------------------
#define XR_F4 (MM*DD/4)      // 2097152 float4
#define WR_F4 (DD*DD/4)      // 262144 float4

__global__ __launch_bounds__(256)
void round_prep(const float* __restrict__ x,
                const float* __restrict__ Wq, const float* __restrict__ Wk,
                const float* __restrict__ Wv, const float* __restrict__ Wo,
                float* __restrict__ xr, float* __restrict__ wr)
{
    const int idx = blockIdx.x * blockDim.x + threadIdx.x;
    const float4* src;
    float4* dst;
    int off;
    if (idx < XR_F4) {
        src = (const float4*)x; dst = (float4*)xr; off = idx;
    } else {
        const int t = idx - XR_F4;
        const int sel = t >> 18;            // WR_F4 = 2^18
        off = t & (WR_F4 - 1);
        const float* ws = (sel == 0) ? Wq : (sel == 1) ? Wk : (sel == 2) ? Wv : Wo;
        src = (const float4*)ws;
        dst = (float4*)(wr + (size_t)sel * DD * DD);
    }
    float4 v = src[off];
    float4 o;
    o.x = __uint_as_float(cvt_tf32(v.x));
    o.y = __uint_as_float(cvt_tf32(v.y));
    o.z = __uint_as_float(cvt_tf32(v.z));
    o.w = __uint_as_float(cvt_tf32(v.w));
    dst[off] = o;
}

// ---------------------------------------------------------------------------
// tf32 warp-MMA GEMM body. Inputs pre-rounded -> raw smem bits into MMA.
// QKV=true also RN-rounds its outputs (consumed by tf32 MMAs downstream).
// ---------------------------------------------------------------------------
#define GSTAGE (128*36)

template <bool QKV>
__device__ __forceinline__
void gemm_body(float* smemf,
               const float* __restrict__ A, const float* __restrict__ W,
               const float* __restrict__ bias, float* __restrict__ C)
{
    float* As = smemf;
    float* Ws = smemf + 3*GSTAGE;
    const uint32_t As_u = smem_u32(As);
    const uint32_t Ws_u = smem_u32(Ws);

    const int tid  = threadIdx.x;
    const int lane = tid & 31, wid = tid >> 5;
    const int q = lane & 3, g = lane >> 2;
    const int mbase = (wid >> 2) * 64;
    const int nbase = (wid & 3) * 32;
    const int rowBase = blockIdx.y * 128;
    const int colBase = blockIdx.x * 128;

    int lr[4], lg[4];
    #pragma unroll
    for (int i = 0; i < 4; i++) { int c = tid + i*256; lr[i] = c >> 3; lg[i] = c & 7; }

    float d[4][4][4];
    #pragma unroll
    for (int mt = 0; mt < 4; mt++)
        #pragma unroll
        for (int nt = 0; nt < 4; nt++)
            #pragma unroll
            for (int e = 0; e < 4; e++) d[mt][nt][e] = 0.f;

    auto issue = [&](int kt) {
        const int slot = kt % 3;
        const uint32_t adst = As_u + (uint32_t)(slot * GSTAGE) * 4u;
        const uint32_t wdst = Ws_u + (uint32_t)(slot * GSTAGE) * 4u;
        #pragma unroll
        for (int i = 0; i < 4; i++) {
            const uint32_t off = (uint32_t)(lr[i]*36 + lg[i]*4) * 4u;
            CP_ASYNC16(adst + off, A + (size_t)(rowBase + lr[i])*DD + kt*32 + lg[i]*4);
            CP_ASYNC16(wdst + off, W + (size_t)(colBase + lr[i])*DD + kt*32 + lg[i]*4);
        }
        CP_COMMIT();
    };

    issue(0);
    issue(1);

    for (int kt = 0; kt < 32; kt++) {
        if (kt == 31) CP_WAIT0(); else CP_WAIT1();
        __syncthreads();
        if (kt + 2 < 32) issue(kt + 2);

        const float* A_s = As + (kt % 3) * GSTAGE;
        const float* W_s = Ws + (kt % 3) * GSTAGE;
        #pragma unroll
        for (int ks = 0; ks < 4; ks++) {
            uint32_t af[4][4], bf[4][2];
            #pragma unroll
            for (int mt = 0; mt < 4; mt++) {
                const int r0 = mbase + mt*16 + g;
                af[mt][0] = __float_as_uint(A_s[r0*36      + ks*8 + q]);
                af[mt][1] = __float_as_uint(A_s[(r0+8)*36  + ks*8 + q]);
                af[mt][2] = __float_as_uint(A_s[r0*36      + ks*8 + q + 4]);
                af[mt][3] = __float_as_uint(A_s[(r0+8)*36  + ks*8 + q + 4]);
            }
            #pragma unroll
            for (int nt = 0; nt < 4; nt++) {
                const int n0 = nbase + nt*8 + g;
                bf[nt][0] = __float_as_uint(W_s[n0*36 + ks*8 + q]);
                bf[nt][1] = __float_as_uint(W_s[n0*36 + ks*8 + q + 4]);
            }
            #pragma unroll
            for (int mt = 0; mt < 4; mt++)
                #pragma unroll
                for (int nt = 0; nt < 4; nt++)
                    mma_tf32(d[mt][nt], af[mt], bf[nt]);
        }
    }

    #pragma unroll
    for (int nt = 0; nt < 4; nt++) {
        const int n0 = colBase + nbase + nt*8 + 2*q;
        const float b0 = bias[n0], b1 = bias[n0 + 1];
        #pragma unroll
        for (int mt = 0; mt < 4; mt++) {
            const int m0 = rowBase + mbase + mt*16 + g;
            #pragma unroll
            for (int half = 0; half < 2; half++) {
                const int m = m0 + half*8;
                float2 o;
                if (QKV) {
                    // round once here so attention can use raw bits
                    o.x = __uint_as_float(cvt_tf32(d[mt][nt][half*2 + 0] + b0));
                    o.y = __uint_as_float(cvt_tf32(d[mt][nt][half*2 + 1] + b1));
                    const int b  = m >> 11;
                    const int s  = m & (SS - 1);
                    const int h  = n0 >> 6;
                    const int hd = n0 & 63;
                    *(float2*)(C + (((size_t)(b*HH + h)*SS + s)*HD + hd)) = o;
                } else {
                    o.x = d[mt][nt][half*2 + 0] + b0;
                    o.y = d[mt][nt][half*2 + 1] + b1;
                    *(float2*)(C + (size_t)m*DD + n0) = o;
                }
            }
        }
    }
}

__global__ __launch_bounds__(256, 2)
void gemm_qkv(const float* __restrict__ A, const float* __restrict__ Wr,
              const float* __restrict__ b0, const float* __restrict__ b1,
              const float* __restrict__ b2,
              float* __restrict__ C0, float* __restrict__ C1, float* __restrict__ C2)
{
    extern __shared__ float smemf[];
    const int z = blockIdx.z;
    const float* W = Wr + (size_t)z * DD * DD;
    const float* b = (z == 0) ? b0 : (z == 1) ? b1 : b2;
    float*       C = (z == 0) ? C0 : (z == 1) ? C1 : C2;
    gemm_body<true>(smemf, A, W, b, C);
}

__global__ __launch_bounds__(256, 2)
void gemm_out(const float* __restrict__ A, const float* __restrict__ W,
              const float* __restrict__ bias, float* __restrict__ C)
{
    extern __shared__ float smemf[];
    gemm_body<false>(smemf, A, W, bias, C);
}

// ---------------------------------------------------------------------------
// tf32 warp-MMA flash-attention, v3. Inputs pre-rounded -> cvt-free K/V/Q
// fragment paths; only post-exp P needs cvt. ctx written tf32-rounded.
// ---------------------------------------------------------------------------
#define KSTR 68
#define VSTR 72
#define QSTR 72
#define KBUF (64*KSTR)
#define VBUF (64*VSTR)

__global__ __launch_bounds__(256, 2)
void attn_mma(const float* __restrict__ Q, const float* __restrict__ K,
              const float* __restrict__ V, float* __restrict__ ctx)
{
    extern __shared__ float sf[];
    float* Qs = sf;                    // [128][72] permuted-pair layout
    float* Ks = sf + 128*QSTR;         // [2][64][68]
    float* Vs = Ks + 2*KBUF;           // [2][64][72]
    const uint32_t Ks_u = smem_u32(Ks);
    const uint32_t Vs_u = smem_u32(Vs);

    const int tid  = threadIdx.x;
    const int lane = tid & 31, wid = tid >> 5;
    const int q = lane & 3, g = lane >> 2;
    const int bh = blockIdx.y, qt = blockIdx.x;

    const float* Qb = Q + (size_t)bh*SS*HD + (size_t)qt*128*HD;
    const float* Kb = K + (size_t)bh*SS*HD;
    const float* Vb = V + (size_t)bh*SS*HD;

    // Q pre-rounded; *0.125 is exact (power of 2). Store pair-permuted.
    #pragma unroll
    for (int i = 0; i < 8; i++) {
        const int c = tid + i*256;
        const int r = c >> 4, d0 = (c & 15) * 4;
        float4 v = *(const float4*)(Qb + r*HD + d0);
        const int base = (d0 & ~7) + ((d0 & 4) ? 1 : 0);
        Qs[r*QSTR + base + 0] = v.x * 0.125f;
        Qs[r*QSTR + base + 2] = v.y * 0.125f;
        Qs[r*QSTR + base + 4] = v.z * 0.125f;
        Qs[r*QSTR + base + 6] = v.w * 0.125f;
    }

    auto issue_kv = [&](int kt) {
        const int buf = kt & 1;
        #pragma unroll
        for (int i = 0; i < 4; i++) {
            const int c = tid + i*256;
            const int r = c >> 4, d0 = (c & 15) * 4;
            CP_ASYNC16(Ks_u + (uint32_t)(buf*KBUF + r*KSTR + d0)*4u,
                       Kb + (size_t)(kt*64 + r)*HD + d0);
            CP_ASYNC16(Vs_u + (uint32_t)(buf*VBUF + r*VSTR + d0)*4u,
                       Vb + (size_t)(kt*64 + r)*HD + d0);
        }
        CP_COMMIT();
    };

    const int r0 = wid*16 + g;

    float m0 = -1e30f, m1 = -1e30f, l0 = 0.f, l1 = 0.f;
    float o[8][4];
    #pragma unroll
    for (int nt = 0; nt < 8; nt++)
        #pragma unroll
        for (int e = 0; e < 4; e++) o[nt][e] = 0.f;

    issue_kv(0);

    const int srcA = (lane & ~3) | (q >> 1);
    const int srcB = srcA + 2;
    const bool hi  = (q & 1) != 0;

    for (int kt = 0; kt < SS/64; kt++) {
        CP_WAIT0();
        __syncthreads();
        if (kt + 1 < SS/64) issue_kv(kt + 1);

        const float* Kc = Ks + (kt & 1) * KBUF;
        const float* Vc = Vs + (kt & 1) * VBUF;

        // --- QK^T ---
        float s[8][4];
        #pragma unroll
        for (int nt = 0; nt < 8; nt++)
            #pragma unroll
            for (int e = 0; e < 4; e++) s[nt][e] = 0.f;

        #pragma unroll
        for (int ks = 0; ks < 8; ks++) {
            uint32_t a[4];
            float2 qa = *(const float2*)(Qs + r0*QSTR     + ks*8 + 2*q);
            float2 qb = *(const float2*)(Qs + (r0+8)*QSTR + ks*8 + 2*q);
            a[0] = __float_as_uint(qa.x);
            a[1] = __float_as_uint(qb.x);
            a[2] = __float_as_uint(qa.y);
            a[3] = __float_as_uint(qb.y);
            #pragma unroll
            for (int nt = 0; nt < 8; nt++) {
                uint32_t b[2];
                b[0] = __float_as_uint(Kc[(nt*8 + g)*KSTR + ks*8 + q]);
                b[1] = __float_as_uint(Kc[(nt*8 + g)*KSTR + ks*8 + q + 4]);
                mma_tf32(s[nt], a, b);
            }
        }

        // --- online softmax ---
        float mx0 = -1e30f, mx1 = -1e30f;
        #pragma unroll
        for (int nt = 0; nt < 8; nt++) {
            mx0 = fmaxf(mx0, fmaxf(s[nt][0], s[nt][1]));
            mx1 = fmaxf(mx1, fmaxf(s[nt][2], s[nt][3]));
        }
        mx0 = fmaxf(mx0, __shfl_xor_sync(0xffffffffu, mx0, 1));
        mx0 = fmaxf(mx0, __shfl_xor_sync(0xffffffffu, mx0, 2));
        mx1 = fmaxf(mx1, __shfl_xor_sync(0xffffffffu, mx1, 1));
        mx1 = fmaxf(mx1, __shfl_xor_sync(0xffffffffu, mx1, 2));

        const float mn0 = fmaxf(m0, mx0), mn1 = fmaxf(m1, mx1);
        const float al0 = __expf(m0 - mn0), al1 = __expf(m1 - mn1);

        float sum0 = 0.f, sum1 = 0.f;
        #pragma unroll
        for (int nt = 0; nt < 8; nt++) {
            s[nt][0] = __expf(s[nt][0] - mn0);
            s[nt][1] = __expf(s[nt][1] - mn0);
            s[nt][2] = __expf(s[nt][2] - mn1);
            s[nt][3] = __expf(s[nt][3] - mn1);
            sum0 += s[nt][0] + s[nt][1];
            sum1 += s[nt][2] + s[nt][3];
        }
        sum0 += __shfl_xor_sync(0xffffffffu, sum0, 1);
        sum0 += __shfl_xor_sync(0xffffffffu, sum0, 2);
        sum1 += __shfl_xor_sync(0xffffffffu, sum1, 1);
        sum1 += __shfl_xor_sync(0xffffffffu, sum1, 2);

        l0 = l0 * al0 + sum0;  m0 = mn0;
        l1 = l1 * al1 + sum1;  m1 = mn1;

        #pragma unroll
        for (int nt = 0; nt < 8; nt++) {
            o[nt][0] *= al0; o[nt][1] *= al0;
            o[nt][2] *= al1; o[nt][3] *= al1;
        }

        // --- PV: a-frag via shuffles ---
        #pragma unroll
        for (int ks = 0; ks < 8; ks++) {
            const float e0 = s[ks][0], e1 = s[ks][1], e2 = s[ks][2], e3 = s[ks][3];
            const float v0a = __shfl_sync(0xffffffffu, e0, srcA);
            const float v1a = __shfl_sync(0xffffffffu, e1, srcA);
            const float v0b = __shfl_sync(0xffffffffu, e0, srcB);
            const float v1b = __shfl_sync(0xffffffffu, e1, srcB);
            const float v2a = __shfl_sync(0xffffffffu, e2, srcA);
            const float v3a = __shfl_sync(0xffffffffu, e3, srcA);
            const float v2b = __shfl_sync(0xffffffffu, e2, srcB);
            const float v3b = __shfl_sync(0xffffffffu, e3, srcB);
            uint32_t a[4];
            a[0] = cvt_tf32(hi ? v1a : v0a);
            a[1] = cvt_tf32(hi ? v3a : v2a);
            a[2] = cvt_tf32(hi ? v1b : v0b);
            a[3] = cvt_tf32(hi ? v3b : v2b);
            #pragma unroll
            for (int nt = 0; nt < 8; nt++) {
                uint32_t b[2];
                b[0] = __float_as_uint(Vc[(ks*8 + q)*VSTR     + nt*8 + g]);
                b[1] = __float_as_uint(Vc[(ks*8 + q + 4)*VSTR + nt*8 + g]);
                mma_tf32(o[nt], a, b);
            }
        }
    }

    // normalize + RN-round + write ctx in [B,S,D]
    const float inv0 = 1.f / l0, inv1 = 1.f / l1;
    const int b = bh >> 4, h = bh & 15;
    const int row0 = qt*128 + r0;
    float* dst0 = ctx + ((size_t)(b*SS + row0))*DD + h*64;
    float* dst1 = ctx + ((size_t)(b*SS + row0 + 8))*DD + h*64;
    #pragma unroll
    for (int nt = 0; nt < 8; nt++) {
        float2 w0, w1;
        w0.x = __uint_as_float(cvt_tf32(o[nt][0]*inv0));
        w0.y = __uint_as_float(cvt_tf32(o[nt][1]*inv0));
        w1.x = __uint_as_float(cvt_tf32(o[nt][2]*inv1));
        w1.y = __uint_as_float(cvt_tf32(o[nt][3]*inv1));
        *(float2*)(dst0 + nt*8 + 2*q) = w0;
        *(float2*)(dst1 + nt*8 + 2*q) = w1;
    }
}

// ---------------------------------------------------------------------------
extern "C" void kernel_launch(void* const* d_in, const int* in_sizes, int n_in,
                              void* d_out, int out_size)
{
    const float* x  = (const float*)d_in[0];
    const float* Wq = (const float*)d_in[1];
    const float* bq = (const float*)d_in[2];
    const float* Wk = (const float*)d_in[3];
    const float* bk = (const float*)d_in[4];
    const float* Wv = (const float*)d_in[5];
    const float* bv = (const float*)d_in[6];
    const float* Wo = (const float*)d_in[7];
    const float* bo = (const float*)d_in[8];

    float *q, *k, *v, *ctx, *xr, *wr;
    cudaGetSymbolAddress((void**)&q,   g_q);
    cudaGetSymbolAddress((void**)&k,   g_k);
    cudaGetSymbolAddress((void**)&v,   g_v);
    cudaGetSymbolAddress((void**)&ctx, g_ctx);
    cudaGetSymbolAddress((void**)&xr,  g_xr);
    cudaGetSymbolAddress((void**)&wr,  g_wr);

    const int smem_gemm = 3 * GSTAGE * 2 * sizeof(float);               // 110592
    const int smem_attn = (128*QSTR + 2*KBUF + 2*VBUF) * sizeof(float); // 108544
    cudaFuncSetAttribute(gemm_qkv,
                         cudaFuncAttributeMaxDynamicSharedMemorySize, smem_gemm);
    cudaFuncSetAttribute(gemm_out,
                         cudaFuncAttributeMaxDynamicSharedMemorySize, smem_gemm);
    cudaFuncSetAttribute(attn_mma,
                         cudaFuncAttributeMaxDynamicSharedMemorySize, smem_attn);

    round_prep<<<(XR_F4 + 4*WR_F4) / 256, 256>>>(x, Wq, Wk, Wv, Wo, xr, wr);

    dim3 qkvgrid(DD/128, MM/128, 3);
    gemm_qkv<<<qkvgrid, 256, smem_gemm>>>(xr, wr, bq, bk, bv, q, k, v);

    dim3 agrid(SS/128, BB*HH);
    attn_mma<<<agrid, 256, smem_attn>>>(q, k, v, ctx);

    dim3 ogrid(DD/128, MM/128);
    gemm_out<<<ogrid, 256, smem_gemm>>>(ctx, wr + (size_t)3*DD*DD, bo, (float*)d_out);
}